// round 9
// baseline (speedup 1.0000x reference)
#include <cuda_runtime.h>
#include <math.h>

// Problem constants
#define BATCH 256
#define SEQLEN 512
#define OBS 64
#define NNEUR 1024
#define ACT 64
#define KTOT (NNEUR + OBS)
#define NBLK 128             // persistent CTAs, all co-resident (148 SMs)

#define BETA_C 0.9f
#define VTH_C 1.0f

// Ordering candidate this round: SPLIT-K(2) — two ascending 512-halves,
// combined serially (P0 + P1).
#define KHALF 512

// ---------------- device scratch (static; no allocations) ----------------
__device__ float g_Wstk[KTOT * NNEUR];    // rows 0..1023: W_rec.T ; rows 1024..1087: W_in.T
__device__ float g_WoutT[NNEUR * ACT];    // (k, a)
__device__ float g_vA[BATCH * NNEUR];
__device__ float g_vB[BATCH * NNEUR];
__device__ float g_sA[BATCH * NNEUR];
__device__ float g_sB[BATCH * NNEUR];
__device__ unsigned g_count = 0;
__device__ unsigned g_sense = 0;          // monotonic phase; replay-safe

// ---------------- software grid barrier (NBLK co-resident CTAs) ----------------
__device__ __forceinline__ void grid_barrier() {
    __syncthreads();
    if (threadIdx.x == 0) {
        unsigned s = *(volatile unsigned*)&g_sense;
        __threadfence();
        if (atomicAdd(&g_count, 1u) == NBLK - 1u) {
            g_count = 0;
            __threadfence();
            atomicExch(&g_sense, s + 1u);
        } else {
            while (*(volatile unsigned*)&g_sense == s) {}
        }
        __threadfence();
    }
    __syncthreads();
}

// ---------------- prep: tiled transpose into device scratch ----------------
__global__ void transpose_kernel(const float* __restrict__ src, int dst_sel,
                                 int rows, int cols) {
    float* dst = (dst_sel == 0) ? g_Wstk
               : (dst_sel == 1) ? (g_Wstk + NNEUR * NNEUR)
                                : g_WoutT;
    __shared__ float tile[32][33];
    int x = blockIdx.x * 32 + threadIdx.x;
    int y0 = blockIdx.y * 32;
#pragma unroll
    for (int j = 0; j < 32; j += 8) {
        int y = y0 + threadIdx.y + j;
        if (x < cols && y < rows)
            tile[threadIdx.y + j][threadIdx.x] = src[(size_t)y * cols + x];
    }
    __syncthreads();
    int xo = blockIdx.y * 32 + threadIdx.x;
    int yo0 = blockIdx.x * 32;
#pragma unroll
    for (int j = 0; j < 32; j += 8) {
        int yo = yo0 + threadIdx.y + j;
        if (xo < rows && yo < cols)
            dst[(size_t)yo * rows + xo] = tile[threadIdx.x][threadIdx.y + j];
    }
}

__global__ void zero_state_kernel() {
    int idx = blockIdx.x * blockDim.x + threadIdx.x;
    if (idx < BATCH * NNEUR) {
        g_vA[idx] = 0.0f;
        g_sA[idx] = 0.0f;
    }
}

// ---------------- persistent time-loop kernel ----------------
// Numerics contract for the FEEDBACK path (do not reorder):
//  * recurrent sum: split-K(2): k=[0,512) and [512,1024), each an ascending
//    FMA chain; combined P0 + P1 with one __fadd_rn.
//  * input projection: single ascending k=0..63 FMA chain.
//  * state update, no contraction: v' = (((0.9f*v) + accR) + accI) - s.
//  * spike: s' = (v' > 1.0f).
// The action head does NOT feed back -> its ordering is free (split-k tree).
__global__ __launch_bounds__(256, 1) void lif_persistent(
        const float* __restrict__ inputs, float* __restrict__ out) {
    __shared__ float As[2][16][36];     // [stage][kk][b]
    __shared__ float Bs[2][16][68];     // [stage][kk][i]
    __shared__ float sv[4][NNEUR];      // out-phase v rows (16 KB)
    __shared__ float red[2][4][ACT];    // out-phase partials

    const int tid = threadIdx.x;
    const int tx = tid & 15;            // neuron groups (TN=4)
    const int ty = tid >> 4;            // batch pairs  (TM=2)
    const int bi0 = (blockIdx.x & 15) * 64;
    const int bb0 = (blockIdx.x >> 4) * 32;

    const int lb = tid >> 3;            // A-tile: batch 0..31
    const int lk = (tid & 7) * 2;       // A-tile: k pair
    const int wk = tid >> 4;            // B-tile: k 0..15
    const int wi = (tid & 15) * 4;      // B-tile: neuron quad

    for (int t = 0; t < SEQLEN; ++t) {
        const float* __restrict__ vIn  = (t & 1) ? g_vB : g_vA;
        float* __restrict__       vOut = (t & 1) ? g_vA : g_vB;
        const float* __restrict__ sIn  = (t & 1) ? g_sB : g_sA;
        float* __restrict__       sOut = (t & 1) ? g_sA : g_sB;

        // ======== phase A1: recurrent GEMM (64 blocks, double-buffered) ========
        float accP[2][4] = {{0.f,0.f,0.f,0.f},{0.f,0.f,0.f,0.f}};
        float accQ[2][4];

        float2 av = __ldcg(reinterpret_cast<const float2*>(
                        &sIn[(bb0 + lb) * NNEUR + lk]));
        float4 bv = *reinterpret_cast<const float4*>(
                        &g_Wstk[(size_t)wk * NNEUR + bi0 + wi]);
        As[0][lk][lb] = av.x;
        As[0][lk + 1][lb] = av.y;
        *reinterpret_cast<float4*>(&Bs[0][wk][wi]) = bv;

        for (int blk = 0; blk < 64; ++blk) {
            const int st = blk & 1;
            __syncthreads();                      // stage st ready for all warps
            if (blk < 63) {
                const int k0n = (blk + 1) * 16;
                av = __ldcg(reinterpret_cast<const float2*>(
                        &sIn[(bb0 + lb) * NNEUR + k0n + lk]));
                bv = *reinterpret_cast<const float4*>(
                        &g_Wstk[(size_t)(k0n + wk) * NNEUR + bi0 + wi]);
            }
            if (blk == 32) {                      // split-K(2) boundary at k=512
#pragma unroll
                for (int m = 0; m < 2; ++m)
#pragma unroll
                    for (int n = 0; n < 4; ++n) {
                        accQ[m][n] = accP[m][n];
                        accP[m][n] = 0.0f;
                    }
            }
#pragma unroll
            for (int kk = 0; kk < 16; ++kk) {
                float2 a = *reinterpret_cast<const float2*>(&As[st][kk][ty * 2]);
                float4 b = *reinterpret_cast<const float4*>(&Bs[st][kk][tx * 4]);
                accP[0][0] = __fmaf_rn(a.x, b.x, accP[0][0]);
                accP[0][1] = __fmaf_rn(a.x, b.y, accP[0][1]);
                accP[0][2] = __fmaf_rn(a.x, b.z, accP[0][2]);
                accP[0][3] = __fmaf_rn(a.x, b.w, accP[0][3]);
                accP[1][0] = __fmaf_rn(a.y, b.x, accP[1][0]);
                accP[1][1] = __fmaf_rn(a.y, b.y, accP[1][1]);
                accP[1][2] = __fmaf_rn(a.y, b.z, accP[1][2]);
                accP[1][3] = __fmaf_rn(a.y, b.w, accP[1][3]);
            }
            if (blk < 63) {
                const int sn = st ^ 1;
                As[sn][lk][lb] = av.x;
                As[sn][lk + 1][lb] = av.y;
                *reinterpret_cast<float4*>(&Bs[sn][wk][wi]) = bv;
            }
        }
        float accS[2][4];
#pragma unroll
        for (int m = 0; m < 2; ++m)
#pragma unroll
            for (int n = 0; n < 4; ++n)
                accS[m][n] = __fadd_rn(accQ[m][n], accP[m][n]);  // P0 + P1

        // ======== phase A2: input projection (4 blocks, ascending chain) ========
        float accI[2][4] = {{0.f,0.f,0.f,0.f},{0.f,0.f,0.f,0.f}};
        {
            av = *reinterpret_cast<const float2*>(
                    &inputs[((size_t)(bb0 + lb) * SEQLEN + t) * OBS + lk]);
            bv = *reinterpret_cast<const float4*>(
                    &g_Wstk[(size_t)(NNEUR + wk) * NNEUR + bi0 + wi]);
            // safe to overwrite stage 0: all warps passed blk-63's top sync,
            // so every reader of stage 0 (last used at blk 62) is done.
            As[0][lk][lb] = av.x;
            As[0][lk + 1][lb] = av.y;
            *reinterpret_cast<float4*>(&Bs[0][wk][wi]) = bv;
            for (int blk = 0; blk < 4; ++blk) {
                const int st = blk & 1;
                __syncthreads();
                if (blk < 3) {
                    const int kc = (blk + 1) * 16;
                    av = *reinterpret_cast<const float2*>(
                            &inputs[((size_t)(bb0 + lb) * SEQLEN + t) * OBS + kc + lk]);
                    bv = *reinterpret_cast<const float4*>(
                            &g_Wstk[(size_t)(NNEUR + kc + wk) * NNEUR + bi0 + wi]);
                }
#pragma unroll
                for (int kk = 0; kk < 16; ++kk) {
                    float2 a = *reinterpret_cast<const float2*>(&As[st][kk][ty * 2]);
                    float4 b = *reinterpret_cast<const float4*>(&Bs[st][kk][tx * 4]);
                    accI[0][0] = __fmaf_rn(a.x, b.x, accI[0][0]);
                    accI[0][1] = __fmaf_rn(a.x, b.y, accI[0][1]);
                    accI[0][2] = __fmaf_rn(a.x, b.z, accI[0][2]);
                    accI[0][3] = __fmaf_rn(a.x, b.w, accI[0][3]);
                    accI[1][0] = __fmaf_rn(a.y, b.x, accI[1][0]);
                    accI[1][1] = __fmaf_rn(a.y, b.y, accI[1][1]);
                    accI[1][2] = __fmaf_rn(a.y, b.z, accI[1][2]);
                    accI[1][3] = __fmaf_rn(a.y, b.w, accI[1][3]);
                }
                if (blk < 3) {
                    const int sn = st ^ 1;
                    As[sn][lk][lb] = av.x;
                    As[sn][lk + 1][lb] = av.y;
                    *reinterpret_cast<float4*>(&Bs[sn][wk][wi]) = bv;
                }
            }
        }

        // ---- epilogue: v' = (((0.9*v) + accS) + accI) - s  — strictly NO fma ----
#pragma unroll
        for (int m = 0; m < 2; ++m) {
            int b = bb0 + ty * 2 + m;
#pragma unroll
            for (int n = 0; n < 4; ++n) {
                int i = bi0 + tx * 4 + n;
                int idx = b * NNEUR + i;
                float so = __ldcg(&sIn[idx]);
                float vl = __ldcg(&vIn[idx]);
                float leak = __fmul_rn(BETA_C, vl);
                float v = __fsub_rn(
                            __fadd_rn(__fadd_rn(leak, accS[m][n]), accI[m][n]),
                            so);
                vOut[idx] = v;
                sOut[idx] = (v > VTH_C) ? 1.0f : 0.0f;
            }
        }

        grid_barrier();

        // ======== phase B: action head on CTAs 0..63 (4 rows each) ========
        // Non-feedback: free ordering (split-k=2 + tree combine).
        // CTAs 64..127 skip straight to the next step's GEMM (touches only
        // opposite-parity state buffers — no hazard with this phase).
        if (blockIdx.x < 64) {
            const int r0 = blockIdx.x * 4;
            const float4* vs = reinterpret_cast<const float4*>(&vOut[(size_t)r0 * NNEUR]);
            float4* dstv = reinterpret_cast<float4*>(&sv[0][0]);
#pragma unroll
            for (int i = 0; i < 4; ++i)
                dstv[tid + i * 256] = __ldcg(&vs[tid + i * 256]);
            __syncthreads();

            const int a = tid & 63;
            const int half = (tid >> 6) & 1;
            const int rp = tid >> 7;               // row pair 0/1
            const int kb = half * 512;
            float a0 = 0.f, a1 = 0.f;
#pragma unroll 8
            for (int k = 0; k < 512; ++k) {
                float w = g_WoutT[(size_t)(kb + k) * ACT + a];
                a0 = __fmaf_rn(sv[rp * 2][kb + k], w, a0);
                a1 = __fmaf_rn(sv[rp * 2 + 1][kb + k], w, a1);
            }
            red[half][rp * 2][a] = a0;
            red[half][rp * 2 + 1][a] = a1;
            __syncthreads();

            const int rr = tid >> 6;               // 0..3
            const int aa = tid & 63;
            float s2 = __fadd_rn(red[0][rr][aa], red[1][rr][aa]);
            out[((size_t)(r0 + rr) * SEQLEN + t) * ACT + aa] = tanhf(s2);
            // sv/red reused only after the NEXT grid_barrier + syncs.
        }
    }
}

// ---------------- launch ----------------
extern "C" void kernel_launch(void* const* d_in, const int* in_sizes, int n_in,
                              void* d_out, int out_size) {
    const float* inputs = (const float*)d_in[0];   // (B, T, OBS)
    const float* W_rec  = (const float*)d_in[1];   // (N, N)
    const float* W_in   = (const float*)d_in[2];   // (N, OBS)
    const float* W_out  = (const float*)d_in[3];   // (ACT, N)
    float* out = (float*)d_out;                    // (B, T, ACT)

    dim3 tb(32, 8);
    transpose_kernel<<<dim3(NNEUR / 32, NNEUR / 32), tb>>>(W_rec, 0, NNEUR, NNEUR);
    transpose_kernel<<<dim3(OBS / 32, NNEUR / 32), tb>>>(W_in, 1, NNEUR, OBS);
    transpose_kernel<<<dim3(NNEUR / 32, ACT / 32), tb>>>(W_out, 2, ACT, NNEUR);
    zero_state_kernel<<<(BATCH * NNEUR) / 256, 256>>>();

    lif_persistent<<<NBLK, 256>>>(inputs, out);
}

// round 10
// speedup vs baseline: 1.0921x; 1.0921x over previous
#include <cuda_runtime.h>
#include <math.h>

// Problem constants
#define BATCH 256
#define SEQLEN 512
#define OBS 64
#define NNEUR 1024
#define ACT 64
#define KTOT (NNEUR + OBS)
#define NBLK 256             // persistent CTAs: 2 per SM (<= 148*2), all co-resident

#define BETA_C 0.9f
#define VTH_C 1.0f

// ---------------- device scratch (static; no allocations) ----------------
__device__ float g_Wstk[KTOT * NNEUR];    // rows 0..1023: W_rec.T ; rows 1024..1087: W_in.T
__device__ float g_WoutT[NNEUR * ACT];    // (k, a)
__device__ float g_vA[BATCH * NNEUR];
__device__ float g_vB[BATCH * NNEUR];
__device__ float g_sA[BATCH * NNEUR];
__device__ float g_sB[BATCH * NNEUR];
__device__ unsigned g_count = 0;
__device__ unsigned g_sense = 0;          // monotonic phase; replay-safe

// ---------------- software grid barrier (NBLK co-resident CTAs) ----------------
__device__ __forceinline__ void grid_barrier() {
    __syncthreads();
    if (threadIdx.x == 0) {
        unsigned s = *(volatile unsigned*)&g_sense;
        __threadfence();
        if (atomicAdd(&g_count, 1u) == NBLK - 1u) {
            g_count = 0;
            __threadfence();
            atomicExch(&g_sense, s + 1u);
        } else {
            while (*(volatile unsigned*)&g_sense == s) {}
        }
        __threadfence();
    }
    __syncthreads();
}

// ---------------- prep: tiled transpose into device scratch ----------------
__global__ void transpose_kernel(const float* __restrict__ src, int dst_sel,
                                 int rows, int cols) {
    float* dst = (dst_sel == 0) ? g_Wstk
               : (dst_sel == 1) ? (g_Wstk + NNEUR * NNEUR)
                                : g_WoutT;
    __shared__ float tile[32][33];
    int x = blockIdx.x * 32 + threadIdx.x;
    int y0 = blockIdx.y * 32;
#pragma unroll
    for (int j = 0; j < 32; j += 8) {
        int y = y0 + threadIdx.y + j;
        if (x < cols && y < rows)
            tile[threadIdx.y + j][threadIdx.x] = src[(size_t)y * cols + x];
    }
    __syncthreads();
    int xo = blockIdx.y * 32 + threadIdx.x;
    int yo0 = blockIdx.x * 32;
#pragma unroll
    for (int j = 0; j < 32; j += 8) {
        int yo = yo0 + threadIdx.y + j;
        if (xo < rows && yo < cols)
            dst[(size_t)yo * rows + xo] = tile[threadIdx.x][threadIdx.y + j];
    }
}

__global__ void zero_state_kernel() {
    int idx = blockIdx.x * blockDim.x + threadIdx.x;
    if (idx < BATCH * NNEUR) {
        g_vA[idx] = 0.0f;
        g_sA[idx] = 0.0f;
    }
}

// no-op: positions the persistent kernel as launch #6 so ncu (-s 5 -c 1)
// captures it instead of a prep kernel.
__global__ void nop_kernel() {}

// ---------------- persistent time-loop kernel ----------------
// FROZEN numerics contract for the FEEDBACK path (bitwise-matched to ref):
//  * recurrent sum: split-K(2): k=[0,512) and [512,1024), each an ascending
//    FMA chain; combined P0 + P1 with one __fadd_rn. (Per-accumulator chain
//    order is independent of the tiling; tiles changed vs R9, order did not.)
//  * input projection: single ascending k=0..63 FMA chain.
//  * state update, no contraction: v' = (((0.9f*v) + accR) + accI) - s.
//  * spike: s' = (v' > 1.0f).  State reads via __ldcg (L2-coherent).
// The action head does NOT feed back -> ordering free.
//
// 256 CTAs x 128 threads, 2 CTAs/SM: the two resident CTAs' sync domains are
// independent, so one CTA's __syncthreads / L2-latency bubbles are filled by
// the other CTA's FFMA issue.
__global__ __launch_bounds__(128, 2) void lif_persistent(
        const float* __restrict__ inputs, float* __restrict__ out) {
    __shared__ float As[2][16][36];     // [stage][kk][b]   32 batches
    __shared__ float Bs[2][16][36];     // [stage][kk][i]   32 neurons
    __shared__ float sv[2][NNEUR];      // out-phase v rows
    __shared__ float red[2][2][ACT];    // out-phase partials [khalf][row][act]

    const int tid = threadIdx.x;
    const int tx = tid & 7;             // neuron groups (TN=4) -> 32 i
    const int ty = tid >> 3;            // batch pairs  (TM=2) -> 32 b
    const int bi0 = (blockIdx.x & 31) * 32;   // 32 neuron tiles
    const int bb0 = (blockIdx.x >> 5) * 32;   // 8 batch tiles

    const int lb = tid >> 3;            // A-tile: batch 0..15 (+16 second load)
    const int lk = (tid & 7) * 2;       // A-tile: k pair
    const int wk = tid >> 3;            // B-tile: k 0..15
    const int wi = (tid & 7) * 4;       // B-tile: neuron quad

    for (int t = 0; t < SEQLEN; ++t) {
        const float* __restrict__ vIn  = (t & 1) ? g_vB : g_vA;
        float* __restrict__       vOut = (t & 1) ? g_vA : g_vB;
        const float* __restrict__ sIn  = (t & 1) ? g_sB : g_sA;
        float* __restrict__       sOut = (t & 1) ? g_sA : g_sB;

        // ======== phase A1: recurrent GEMM (64 blocks, double-buffered) ========
        float accP[2][4] = {{0.f,0.f,0.f,0.f},{0.f,0.f,0.f,0.f}};
        float accQ[2][4];

        float2 av0 = __ldcg(reinterpret_cast<const float2*>(
                        &sIn[(bb0 + lb) * NNEUR + lk]));
        float2 av1 = __ldcg(reinterpret_cast<const float2*>(
                        &sIn[(bb0 + lb + 16) * NNEUR + lk]));
        float4 bv = *reinterpret_cast<const float4*>(
                        &g_Wstk[(size_t)wk * NNEUR + bi0 + wi]);
        As[0][lk][lb] = av0.x;  As[0][lk + 1][lb] = av0.y;
        As[0][lk][lb + 16] = av1.x;  As[0][lk + 1][lb + 16] = av1.y;
        *reinterpret_cast<float4*>(&Bs[0][wk][wi]) = bv;

        for (int blk = 0; blk < 64; ++blk) {
            const int st = blk & 1;
            __syncthreads();                      // stage st ready
            if (blk < 63) {
                const int k0n = (blk + 1) * 16;
                av0 = __ldcg(reinterpret_cast<const float2*>(
                        &sIn[(bb0 + lb) * NNEUR + k0n + lk]));
                av1 = __ldcg(reinterpret_cast<const float2*>(
                        &sIn[(bb0 + lb + 16) * NNEUR + k0n + lk]));
                bv = *reinterpret_cast<const float4*>(
                        &g_Wstk[(size_t)(k0n + wk) * NNEUR + bi0 + wi]);
            }
            if (blk == 32) {                      // split-K(2) boundary at k=512
#pragma unroll
                for (int m = 0; m < 2; ++m)
#pragma unroll
                    for (int n = 0; n < 4; ++n) {
                        accQ[m][n] = accP[m][n];
                        accP[m][n] = 0.0f;
                    }
            }
#pragma unroll
            for (int kk = 0; kk < 16; ++kk) {
                float2 a = *reinterpret_cast<const float2*>(&As[st][kk][ty * 2]);
                float4 b = *reinterpret_cast<const float4*>(&Bs[st][kk][tx * 4]);
                accP[0][0] = __fmaf_rn(a.x, b.x, accP[0][0]);
                accP[0][1] = __fmaf_rn(a.x, b.y, accP[0][1]);
                accP[0][2] = __fmaf_rn(a.x, b.z, accP[0][2]);
                accP[0][3] = __fmaf_rn(a.x, b.w, accP[0][3]);
                accP[1][0] = __fmaf_rn(a.y, b.x, accP[1][0]);
                accP[1][1] = __fmaf_rn(a.y, b.y, accP[1][1]);
                accP[1][2] = __fmaf_rn(a.y, b.z, accP[1][2]);
                accP[1][3] = __fmaf_rn(a.y, b.w, accP[1][3]);
            }
            if (blk < 63) {
                const int sn = st ^ 1;
                As[sn][lk][lb] = av0.x;  As[sn][lk + 1][lb] = av0.y;
                As[sn][lk][lb + 16] = av1.x;  As[sn][lk + 1][lb + 16] = av1.y;
                *reinterpret_cast<float4*>(&Bs[sn][wk][wi]) = bv;
            }
        }
        float accS[2][4];
#pragma unroll
        for (int m = 0; m < 2; ++m)
#pragma unroll
            for (int n = 0; n < 4; ++n)
                accS[m][n] = __fadd_rn(accQ[m][n], accP[m][n]);  // P0 + P1

        // ======== phase A2: input projection (4 blocks, ascending chain) ========
        float accI[2][4] = {{0.f,0.f,0.f,0.f},{0.f,0.f,0.f,0.f}};
        {
            const size_t ibase = ((size_t)(bb0 + lb) * SEQLEN + t) * OBS;
            const size_t ibase2 = ((size_t)(bb0 + lb + 16) * SEQLEN + t) * OBS;
            av0 = *reinterpret_cast<const float2*>(&inputs[ibase + lk]);
            av1 = *reinterpret_cast<const float2*>(&inputs[ibase2 + lk]);
            bv = *reinterpret_cast<const float4*>(
                    &g_Wstk[(size_t)(NNEUR + wk) * NNEUR + bi0 + wi]);
            // stage 0 safe: all warps passed blk-63's sync (stage 0 last read at blk 62)
            As[0][lk][lb] = av0.x;  As[0][lk + 1][lb] = av0.y;
            As[0][lk][lb + 16] = av1.x;  As[0][lk + 1][lb + 16] = av1.y;
            *reinterpret_cast<float4*>(&Bs[0][wk][wi]) = bv;
            for (int blk = 0; blk < 4; ++blk) {
                const int st = blk & 1;
                __syncthreads();
                if (blk < 3) {
                    const int kc = (blk + 1) * 16;
                    av0 = *reinterpret_cast<const float2*>(&inputs[ibase + kc + lk]);
                    av1 = *reinterpret_cast<const float2*>(&inputs[ibase2 + kc + lk]);
                    bv = *reinterpret_cast<const float4*>(
                            &g_Wstk[(size_t)(NNEUR + kc + wk) * NNEUR + bi0 + wi]);
                }
#pragma unroll
                for (int kk = 0; kk < 16; ++kk) {
                    float2 a = *reinterpret_cast<const float2*>(&As[st][kk][ty * 2]);
                    float4 b = *reinterpret_cast<const float4*>(&Bs[st][kk][tx * 4]);
                    accI[0][0] = __fmaf_rn(a.x, b.x, accI[0][0]);
                    accI[0][1] = __fmaf_rn(a.x, b.y, accI[0][1]);
                    accI[0][2] = __fmaf_rn(a.x, b.z, accI[0][2]);
                    accI[0][3] = __fmaf_rn(a.x, b.w, accI[0][3]);
                    accI[1][0] = __fmaf_rn(a.y, b.x, accI[1][0]);
                    accI[1][1] = __fmaf_rn(a.y, b.y, accI[1][1]);
                    accI[1][2] = __fmaf_rn(a.y, b.z, accI[1][2]);
                    accI[1][3] = __fmaf_rn(a.y, b.w, accI[1][3]);
                }
                if (blk < 3) {
                    const int sn = st ^ 1;
                    As[sn][lk][lb] = av0.x;  As[sn][lk + 1][lb] = av0.y;
                    As[sn][lk][lb + 16] = av1.x;  As[sn][lk + 1][lb + 16] = av1.y;
                    *reinterpret_cast<float4*>(&Bs[sn][wk][wi]) = bv;
                }
            }
        }

        // ---- epilogue: v' = (((0.9*v) + accS) + accI) - s  — strictly NO fma ----
#pragma unroll
        for (int m = 0; m < 2; ++m) {
            int b = bb0 + ty * 2 + m;
#pragma unroll
            for (int n = 0; n < 4; ++n) {
                int i = bi0 + tx * 4 + n;
                int idx = b * NNEUR + i;
                float so = __ldcg(&sIn[idx]);
                float vl = __ldcg(&vIn[idx]);
                float leak = __fmul_rn(BETA_C, vl);
                float v = __fsub_rn(
                            __fadd_rn(__fadd_rn(leak, accS[m][n]), accI[m][n]),
                            so);
                vOut[idx] = v;
                sOut[idx] = (v > VTH_C) ? 1.0f : 0.0f;
            }
        }

        grid_barrier();

        // ======== phase B: action head on CTAs 0..127 (2 rows each) ========
        // Non-feedback -> free ordering. CTAs 128..255 proceed straight to the
        // next step's GEMM (opposite-parity state buffers; no hazard).
        if (blockIdx.x < 128) {
            const int r0 = blockIdx.x * 2;
            const float4* vs = reinterpret_cast<const float4*>(&vOut[(size_t)r0 * NNEUR]);
            float4* dstv = reinterpret_cast<float4*>(&sv[0][0]);
#pragma unroll
            for (int i = 0; i < 4; ++i)
                dstv[tid + i * 128] = __ldcg(&vs[tid + i * 128]);
            __syncthreads();

            const int a = tid & 63;
            const int h = tid >> 6;             // k-half
            const int kb = h * 512;
            float a0 = 0.f, a1 = 0.f;
#pragma unroll 8
            for (int k = 0; k < 512; ++k) {
                float w = g_WoutT[(size_t)(kb + k) * ACT + a];
                a0 = __fmaf_rn(sv[0][kb + k], w, a0);
                a1 = __fmaf_rn(sv[1][kb + k], w, a1);
            }
            red[h][0][a] = a0;
            red[h][1][a] = a1;
            __syncthreads();

            const int rr = tid >> 6;            // row 0/1
            const int aa = tid & 63;
            float s2 = __fadd_rn(red[0][rr][aa], red[1][rr][aa]);
            out[((size_t)(r0 + rr) * SEQLEN + t) * ACT + aa] = tanhf(s2);
            // sv/red reused only after the NEXT grid_barrier + __syncthreads.
        }
    }
}

// ---------------- launch ----------------
extern "C" void kernel_launch(void* const* d_in, const int* in_sizes, int n_in,
                              void* d_out, int out_size) {
    const float* inputs = (const float*)d_in[0];   // (B, T, OBS)
    const float* W_rec  = (const float*)d_in[1];   // (N, N)
    const float* W_in   = (const float*)d_in[2];   // (N, OBS)
    const float* W_out  = (const float*)d_in[3];   // (ACT, N)
    float* out = (float*)d_out;                    // (B, T, ACT)

    dim3 tb(32, 8);
    transpose_kernel<<<dim3(NNEUR / 32, NNEUR / 32), tb>>>(W_rec, 0, NNEUR, NNEUR);
    transpose_kernel<<<dim3(OBS / 32, NNEUR / 32), tb>>>(W_in, 1, NNEUR, OBS);
    transpose_kernel<<<dim3(NNEUR / 32, ACT / 32), tb>>>(W_out, 2, ACT, NNEUR);
    zero_state_kernel<<<(BATCH * NNEUR) / 256, 256>>>();
    nop_kernel<<<1, 32>>>();   // makes lif_persistent launch #6 for ncu -s 5 -c 1

    lif_persistent<<<NBLK, 128>>>(inputs, out);
}